// round 1
// baseline (speedup 1.0000x reference)
#include <cuda_runtime.h>

#define N_NODES 50000
#define N_EDGES 500000
#define D_NODE  128
#define D_HID   512
#define D_OUT   128

// Scratch for precomputed node transforms: Xs = x @ W1[0:128,:], Xt = x @ W1[128:256,:]
__device__ float g_Xs[(long long)N_NODES * D_HID];
__device__ float g_Xt[(long long)N_NODES * D_HID];

// ---------------------------------------------------------------------------
// Kernel 1: node transform. grid = (ceil(N/32), 2); blockIdx.y selects Xs/Xt.
// Tile: 32 nodes x 512 cols. 256 threads, each computes an 8x8 micro-tile.
// smem: sA[32][128] (x tile) + sW[16][512] (W chunk) = 48KB.
// ---------------------------------------------------------------------------
__global__ __launch_bounds__(256) void node_gemm_kernel(const float* __restrict__ x,
                                                        const float* __restrict__ W1) {
    extern __shared__ float sm[];
    float* sA = sm;            // [32][128]
    float* sW = sm + 32 * 128; // [16][512]

    const int tid   = threadIdx.x;
    const int node0 = blockIdx.x * 32;
    const int which = blockIdx.y;
    const float* W  = W1 + (size_t)which * 128 * 512;
    float* out      = which ? g_Xt : g_Xs;

    // Load x tile [32][128] (clamp node index for the last partial tile)
#pragma unroll
    for (int i = 0; i < 4; i++) {
        int idx = tid + i * 256;       // 1024 float4 total
        int r   = idx >> 5;
        int c4  = idx & 31;
        int node = min(node0 + r, N_NODES - 1);
        reinterpret_cast<float4*>(sA + r * 128)[c4] =
            reinterpret_cast<const float4*>(x + (size_t)node * 128)[c4];
    }

    const int nb = tid & 63, eb = tid >> 6;
    const int ncol = nb * 8, erow = eb * 8;

    float acc[8][8];
#pragma unroll
    for (int i = 0; i < 8; i++)
#pragma unroll
        for (int j = 0; j < 8; j++) acc[i][j] = 0.f;

    for (int k0 = 0; k0 < 128; k0 += 16) {
        // Stage W[k0:k0+16, 0:512] into smem (coalesced float4)
#pragma unroll
        for (int i = 0; i < 8; i++) {
            int idx = tid + i * 256;   // 2048 float4 total
            int kk  = idx >> 7;
            int c4  = idx & 127;
            reinterpret_cast<float4*>(sW + kk * 512)[c4] =
                reinterpret_cast<const float4*>(W + (size_t)(k0 + kk) * 512)[c4];
        }
        __syncthreads();

#pragma unroll
        for (int kk = 0; kk < 16; kk += 4) {
            float4 a4[8];
#pragma unroll
            for (int i = 0; i < 8; i++)
                a4[i] = *reinterpret_cast<const float4*>(sA + (erow + i) * 128 + k0 + kk);
#pragma unroll
            for (int t = 0; t < 4; t++) {
                float4 w0 = *reinterpret_cast<const float4*>(sW + (kk + t) * 512 + ncol);
                float4 w1 = *reinterpret_cast<const float4*>(sW + (kk + t) * 512 + ncol + 4);
                float wv[8] = {w0.x, w0.y, w0.z, w0.w, w1.x, w1.y, w1.z, w1.w};
#pragma unroll
                for (int i = 0; i < 8; i++) {
                    float av = (t == 0) ? a4[i].x : (t == 1) ? a4[i].y : (t == 2) ? a4[i].z : a4[i].w;
#pragma unroll
                    for (int j = 0; j < 8; j++) acc[i][j] = fmaf(av, wv[j], acc[i][j]);
                }
            }
        }
        __syncthreads();
    }

#pragma unroll
    for (int i = 0; i < 8; i++) {
        int node = node0 + erow + i;
        if (node < N_NODES) {
            float4* dst = reinterpret_cast<float4*>(out + (size_t)node * 512 + ncol);
            dst[0] = make_float4(acc[i][0], acc[i][1], acc[i][2], acc[i][3]);
            dst[1] = make_float4(acc[i][4], acc[i][5], acc[i][6], acc[i][7]);
        }
    }
}

// ---------------------------------------------------------------------------
// Kernel 2: per-edge fused MLP. 32 edges per CTA, 256 threads.
// Phase 1: H[32,512] = ea@W1c + Xs[row] + Xt[col] + b1, ReLU  (8x8 tiles)
// Phase 2: out[32,128] = H @ W2 + b2                           (4x4 tiles)
// smem: sEA[32][128] + sW[16][512] + sH[32][512] + idx[64] = ~112.25KB
// ---------------------------------------------------------------------------
__global__ __launch_bounds__(256) void edge_kernel(const float* __restrict__ edge_attr,
                                                   const int*   __restrict__ edge_index,
                                                   const float* __restrict__ W1,
                                                   const float* __restrict__ b1,
                                                   const float* __restrict__ W2,
                                                   const float* __restrict__ b2,
                                                   float* __restrict__ out) {
    extern __shared__ float sm[];
    float* sEA  = sm;                    // [32][128]
    float* sW   = sm + 4096;             // [16][512] phase1 / [32][128] phase2
    float* sH   = sm + 4096 + 8192;      // [32][512]
    int*   sIdx = reinterpret_cast<int*>(sm + 4096 + 8192 + 16384); // row[32]|col[32]

    const int tid = threadIdx.x;
    const int e0  = blockIdx.x * 32;
    const float* W1c = W1 + (size_t)256 * 512;

    if (tid < 32) {
        sIdx[tid]      = edge_index[e0 + tid];            // row (source)
        sIdx[32 + tid] = edge_index[N_EDGES + e0 + tid];  // col (target)
    }
#pragma unroll
    for (int i = 0; i < 4; i++) {
        int idx = tid + i * 256;
        int r = idx >> 5, c4 = idx & 31;
        reinterpret_cast<float4*>(sEA + r * 128)[c4] =
            reinterpret_cast<const float4*>(edge_attr + (size_t)(e0 + r) * 128)[c4];
    }

    // ---------------- Phase 1: GEMM ea @ W1c ----------------
    const int nb = tid & 63, eb = tid >> 6;
    const int ncol = nb * 8, erow = eb * 8;

    float acc[8][8];
#pragma unroll
    for (int i = 0; i < 8; i++)
#pragma unroll
        for (int j = 0; j < 8; j++) acc[i][j] = 0.f;

    for (int k0 = 0; k0 < 128; k0 += 16) {
#pragma unroll
        for (int i = 0; i < 8; i++) {
            int idx = tid + i * 256;
            int kk = idx >> 7, c4 = idx & 127;
            reinterpret_cast<float4*>(sW + kk * 512)[c4] =
                reinterpret_cast<const float4*>(W1c + (size_t)(k0 + kk) * 512)[c4];
        }
        __syncthreads();   // also covers sEA / sIdx on first iteration

#pragma unroll
        for (int kk = 0; kk < 16; kk += 4) {
            float4 a4[8];
#pragma unroll
            for (int i = 0; i < 8; i++)
                a4[i] = *reinterpret_cast<const float4*>(sEA + (erow + i) * 128 + k0 + kk);
#pragma unroll
            for (int t = 0; t < 4; t++) {
                float4 w0 = *reinterpret_cast<const float4*>(sW + (kk + t) * 512 + ncol);
                float4 w1 = *reinterpret_cast<const float4*>(sW + (kk + t) * 512 + ncol + 4);
                float wv[8] = {w0.x, w0.y, w0.z, w0.w, w1.x, w1.y, w1.z, w1.w};
#pragma unroll
                for (int i = 0; i < 8; i++) {
                    float av = (t == 0) ? a4[i].x : (t == 1) ? a4[i].y : (t == 2) ? a4[i].z : a4[i].w;
#pragma unroll
                    for (int j = 0; j < 8; j++) acc[i][j] = fmaf(av, wv[j], acc[i][j]);
                }
            }
        }
        __syncthreads();
    }

    // Epilogue: + Xs[row] + Xt[col] + b1, ReLU, store to sH
    float4 b1a = *reinterpret_cast<const float4*>(b1 + ncol);
    float4 b1b = *reinterpret_cast<const float4*>(b1 + ncol + 4);
#pragma unroll
    for (int i = 0; i < 8; i++) {
        int ie = erow + i;
        int r  = sIdx[ie];
        int c  = sIdx[32 + ie];
        const float4* xs = reinterpret_cast<const float4*>(g_Xs + (size_t)r * 512 + ncol);
        const float4* xt = reinterpret_cast<const float4*>(g_Xt + (size_t)c * 512 + ncol);
        float4 s0 = xs[0], s1 = xs[1], t0 = xt[0], t1 = xt[1];
        float4 h0, h1;
        h0.x = fmaxf(acc[i][0] + s0.x + t0.x + b1a.x, 0.f);
        h0.y = fmaxf(acc[i][1] + s0.y + t0.y + b1a.y, 0.f);
        h0.z = fmaxf(acc[i][2] + s0.z + t0.z + b1a.z, 0.f);
        h0.w = fmaxf(acc[i][3] + s0.w + t0.w + b1a.w, 0.f);
        h1.x = fmaxf(acc[i][4] + s1.x + t1.x + b1b.x, 0.f);
        h1.y = fmaxf(acc[i][5] + s1.y + t1.y + b1b.y, 0.f);
        h1.z = fmaxf(acc[i][6] + s1.z + t1.z + b1b.z, 0.f);
        h1.w = fmaxf(acc[i][7] + s1.w + t1.w + b1b.w, 0.f);
        float4* dst = reinterpret_cast<float4*>(sH + (size_t)ie * 512 + ncol);
        dst[0] = h0;
        dst[1] = h1;
    }
    __syncthreads();

    // ---------------- Phase 2: out = relu(H) @ W2 + b2 ----------------
    const int nb2 = tid & 31, eb2 = tid >> 5;
    const int n2 = nb2 * 4, er2 = eb2 * 4;

    float acc2[4][4];
#pragma unroll
    for (int i = 0; i < 4; i++)
#pragma unroll
        for (int j = 0; j < 4; j++) acc2[i][j] = 0.f;

    for (int k0 = 0; k0 < 512; k0 += 32) {
        // Stage W2[k0:k0+32, 0:128] into sW (reused buffer)
#pragma unroll
        for (int i = 0; i < 4; i++) {
            int idx = tid + i * 256;   // 1024 float4
            int kk = idx >> 5, c4 = idx & 31;
            reinterpret_cast<float4*>(sW + kk * 128)[c4] =
                reinterpret_cast<const float4*>(W2 + (size_t)(k0 + kk) * 128)[c4];
        }
        __syncthreads();

#pragma unroll
        for (int kk = 0; kk < 32; kk += 4) {
            float4 a4[4];
#pragma unroll
            for (int i = 0; i < 4; i++)
                a4[i] = *reinterpret_cast<const float4*>(sH + (er2 + i) * 512 + k0 + kk);
#pragma unroll
            for (int t = 0; t < 4; t++) {
                float4 w = *reinterpret_cast<const float4*>(sW + (kk + t) * 128 + n2);
#pragma unroll
                for (int i = 0; i < 4; i++) {
                    float av = (t == 0) ? a4[i].x : (t == 1) ? a4[i].y : (t == 2) ? a4[i].z : a4[i].w;
                    acc2[i][0] = fmaf(av, w.x, acc2[i][0]);
                    acc2[i][1] = fmaf(av, w.y, acc2[i][1]);
                    acc2[i][2] = fmaf(av, w.z, acc2[i][2]);
                    acc2[i][3] = fmaf(av, w.w, acc2[i][3]);
                }
            }
        }
        __syncthreads();
    }

    float4 b2v = *reinterpret_cast<const float4*>(b2 + n2);
#pragma unroll
    for (int i = 0; i < 4; i++) {
        int e = e0 + er2 + i;
        float4 o = make_float4(acc2[i][0] + b2v.x, acc2[i][1] + b2v.y,
                               acc2[i][2] + b2v.z, acc2[i][3] + b2v.w);
        reinterpret_cast<float4*>(out + (size_t)e * 128)[nb2] = o;
    }
}

// ---------------------------------------------------------------------------
extern "C" void kernel_launch(void* const* d_in, const int* in_sizes, int n_in,
                              void* d_out, int out_size) {
    const float* x  = (const float*)d_in[0];
    const int*   ei = (const int*)d_in[1];
    const float* ea = (const float*)d_in[2];
    const float* W1 = (const float*)d_in[3];
    const float* b1 = (const float*)d_in[4];
    const float* W2 = (const float*)d_in[5];
    const float* b2 = (const float*)d_in[6];
    float* out = (float*)d_out;

    const int smem1 = (32 * 128 + 16 * 512) * 4;                      // 49152
    const int smem2 = (32 * 128 + 16 * 512 + 32 * 512) * 4 + 64 * 4;  // 114944

    cudaFuncSetAttribute(node_gemm_kernel, cudaFuncAttributeMaxDynamicSharedMemorySize, smem1);
    cudaFuncSetAttribute(edge_kernel, cudaFuncAttributeMaxDynamicSharedMemorySize, smem2);

    dim3 g1((N_NODES + 31) / 32, 2);
    node_gemm_kernel<<<g1, 256, smem1>>>(x, W1);
    edge_kernel<<<N_EDGES / 32, 256, smem2>>>(ea, ei, W1, b1, W2, b2, out);
}

// round 5
// speedup vs baseline: 3.8283x; 3.8283x over previous
#include <cuda_runtime.h>
#include <cuda_fp16.h>
#include <cstdint>

#define N_NODES 50000
#define N_EDGES 500000

// ---------------------------------------------------------------------------
// f16 transposed weights (K-major / "col-major B"):
//   g_W1t[n][k]  n<512, k<384   (B for layer 1)
//   g_W2t[n][k]  n<128, k<512   (B for layer 2)
// ---------------------------------------------------------------------------
__device__ __half g_W1t[512 * 384];
__device__ __half g_W2t[128 * 512];

__global__ void cvt_weights_kernel(const float* __restrict__ W1,
                                   const float* __restrict__ W2) {
    int idx = blockIdx.x * blockDim.x + threadIdx.x;
    if (idx < 512 * 384) {
        int n = idx / 384, k = idx % 384;
        g_W1t[idx] = __float2half(W1[k * 512 + n]);
    } else if (idx < 512 * 384 + 128 * 512) {
        int j = idx - 512 * 384;
        int n = j / 512, k = j % 512;
        g_W2t[j] = __float2half(W2[k * 128 + n]);
    }
}

// ---------------------------------------------------------------------------
// PTX helpers (baseline features only — must compile for plain sm_103)
// ---------------------------------------------------------------------------
__device__ __forceinline__ uint32_t s2u(const void* p) {
    uint32_t a;
    asm("{.reg .u64 t; cvta.to.shared.u64 t, %1; cvt.u32.u64 %0, t;}" : "=r"(a) : "l"(p));
    return a;
}
#define CP_ASYNC16(dst, src) \
    asm volatile("cp.async.cg.shared.global [%0], [%1], 16;" :: "r"(dst), "l"(src) : "memory")
#define CP_COMMIT() asm volatile("cp.async.commit_group;" ::: "memory")
#define CP_WAIT(n)  asm volatile("cp.async.wait_group %0;" :: "n"(n) : "memory")

#define LDSM_X4(r0, r1, r2, r3, addr) \
    asm volatile("ldmatrix.sync.aligned.m8n8.x4.shared.b16 {%0,%1,%2,%3}, [%4];" \
                 : "=r"(r0), "=r"(r1), "=r"(r2), "=r"(r3) : "r"(addr))

#define MMA_F16(D, a0, a1, a2, a3, b0, b1) \
    asm volatile("mma.sync.aligned.m16n8k16.row.col.f32.f16.f16.f32 " \
                 "{%0,%1,%2,%3},{%4,%5,%6,%7},{%8,%9},{%0,%1,%2,%3};" \
                 : "+f"((D)[0]), "+f"((D)[1]), "+f"((D)[2]), "+f"((D)[3]) \
                 : "r"(a0), "r"(a1), "r"(a2), "r"(a3), "r"(b0), "r"(b1))

#define STS128(addr, r0, r1, r2, r3) \
    asm volatile("st.shared.v4.b32 [%0], {%1,%2,%3,%4};" \
                 :: "r"(addr), "r"(r0), "r"(r1), "r"(r2), "r"(r3) : "memory")

// ---------------------------------------------------------------------------
// SMEM layout (bytes). A rows padded 384+8 halves = 784 B (conflict-free
// ldmatrix: 784 mod 128 = 16 -> 8 consecutive rows hit 8 distinct 16B groups).
// W1 chunk rows same 784 B pitch; W2 chunk rows 72 halves = 144 B pitch.
// ---------------------------------------------------------------------------
static constexpr uint32_t OFF_A   = 0;          // 128 x 784            = 100352
static constexpr uint32_t OFF_W1  = 100352;     // 2 bufs x (64 x 784)  = 100352
static constexpr uint32_t W1_BUF  = 50176;
static constexpr uint32_t OFF_W2  = 200704;     // 128 x 144            = 18432
static constexpr uint32_t OFF_B1  = 219136;     // 512 f32              = 2048
static constexpr uint32_t OFF_B2  = 221184;     // 128 f32              = 512
static constexpr uint32_t SMEM_TOTAL = 221696;

__global__ __launch_bounds__(256, 1) void edge_mma_kernel(
    const float* __restrict__ x,
    const int*   __restrict__ edge_index,
    const float* __restrict__ edge_attr,
    const float* __restrict__ b1,
    const float* __restrict__ b2,
    float* __restrict__ out)
{
    extern __shared__ __align__(1024) char smem[];
    const uint32_t sb   = s2u(smem);
    const int tid  = threadIdx.x;
    const int warp = tid >> 5, lane = tid & 31;
    const int e0   = blockIdx.x * 128;

    float* sB1 = (float*)(smem + OFF_B1);
    float* sB2 = (float*)(smem + OFF_B2);

    // ---- helper lambdas: cp.async weight chunk loaders ----
    auto issue_w1 = [&](int c, int buf) {
        uint32_t dstb = sb + OFF_W1 + (uint32_t)buf * W1_BUF;
        const __half* src = g_W1t + (size_t)c * 64 * 384;
#pragma unroll
        for (int i = 0; i < 12; i++) {          // 3072 segs / 256 threads
            int j = tid + i * 256;
            int r = j / 48, q = j % 48;
            CP_ASYNC16(dstb + r * 784 + q * 16, src + r * 384 + q * 8);
        }
    };
    auto issue_w2 = [&](int c) {
        uint32_t dstb = sb + OFF_W2;
        const __half* src = g_W2t + c * 64;
#pragma unroll
        for (int i = 0; i < 4; i++) {           // 1024 segs / 256 threads
            int j = tid + i * 256;
            int r = j >> 3, q = j & 7;
            CP_ASYNC16(dstb + r * 144 + q * 16, src + (size_t)r * 512 + q * 8);
        }
    };

    // ---- prologue: kick off weight chunk 0 loads, biases, build A tile ----
    issue_w1(0, 0); CP_COMMIT();
    issue_w2(0);    CP_COMMIT();

    for (int i = tid; i < 512; i += 256) sB1[i] = b1[i];
    for (int i = tid; i < 128; i += 256) sB2[i] = b2[i];

    {
        const int r  = tid & 127;
        const int hb = tid >> 7;               // which half of the 384 cols
        const int e  = min(e0 + r, N_EDGES - 1);
        const int sr = edge_index[e];
        const int sc = edge_index[N_EDGES + e];
        const float* s0 = x + (size_t)sr * 128;
        const float* s1 = x + (size_t)sc * 128;
        const float* s2 = edge_attr + (size_t)e * 128;
#pragma unroll
        for (int j = 0; j < 12; j++) {
            int gcol = hb * 192 + j * 16;
            int which = gcol >> 7;
            int off   = gcol & 127;
            const float* s = (which == 0) ? s0 : (which == 1) ? s1 : s2;
            const float4* p = (const float4*)(s + off);
            float4 v0 = p[0], v1 = p[1], v2 = p[2], v3 = p[3];
            __half2 h0 = __floats2half2_rn(v0.x, v0.y);
            __half2 h1 = __floats2half2_rn(v0.z, v0.w);
            __half2 h2 = __floats2half2_rn(v1.x, v1.y);
            __half2 h3 = __floats2half2_rn(v1.z, v1.w);
            __half2 h4 = __floats2half2_rn(v2.x, v2.y);
            __half2 h5 = __floats2half2_rn(v2.z, v2.w);
            __half2 h6 = __floats2half2_rn(v3.x, v3.y);
            __half2 h7 = __floats2half2_rn(v3.z, v3.w);
            uint32_t d0 = (*(uint32_t*)&h0), d1 = (*(uint32_t*)&h1);
            uint32_t d2 = (*(uint32_t*)&h2), d3 = (*(uint32_t*)&h3);
            uint32_t d4 = (*(uint32_t*)&h4), d5 = (*(uint32_t*)&h5);
            uint32_t d6 = (*(uint32_t*)&h6), d7 = (*(uint32_t*)&h7);
            uint32_t a = sb + OFF_A + r * 784 + gcol * 2;
            STS128(a,      d0, d1, d2, d3);
            STS128(a + 16, d4, d5, d6, d7);
        }
    }
    __syncthreads();

    // ---- per-thread ldmatrix address components ----
    const uint32_t aBase  = sb + OFF_A + (uint32_t)(warp * 16 + (lane & 15)) * 784
                          + ((uint32_t)(lane >> 4) << 4);
    const uint32_t wLane1 = (uint32_t)(lane & 7) * 784 + (((uint32_t)(lane >> 3) & 1) << 4)
                          + (uint32_t)(lane >> 4) * 6272;   // (lane>>4)*8 rows * 784
    const uint32_t wLane2 = (uint32_t)(lane & 7) * 144 + (((uint32_t)(lane >> 3) & 1) << 4)
                          + (uint32_t)(lane >> 4) * 1152;   // (lane>>4)*8 rows * 144
    const int c2i = (lane & 3) * 2;

    float acc2[16][4];
#pragma unroll
    for (int t = 0; t < 16; t++)
#pragma unroll
        for (int j = 0; j < 4; j++) acc2[t][j] = 0.f;

    // ---- main loop over 8 N-chunks of 64 (layer1 N == layer2 K) ----
    for (int c = 0; c < 8; c++) {
        CP_WAIT(1);                    // W1[c] resident (W2[c] may still fly)
        __syncthreads();
        if (c < 7) { issue_w1(c + 1, (c + 1) & 1); CP_COMMIT(); }

        // ----- layer 1: A[128x384] @ W1chunk[384x64] -----
        const uint32_t wb = sb + OFF_W1 + (uint32_t)(c & 1) * W1_BUF + wLane1;
        float acc1[8][4];
#pragma unroll
        for (int t = 0; t < 8; t++)
#pragma unroll
            for (int j = 0; j < 4; j++) acc1[t][j] = 0.f;

#pragma unroll
        for (int s = 0; s < 24; s++) {
            uint32_t a0, a1, a2, a3;
            LDSM_X4(a0, a1, a2, a3, aBase + s * 32);
            uint32_t wrow = wb + s * 32;
#pragma unroll
            for (int tp = 0; tp < 4; tp++) {
                uint32_t b0, b1r, b2r, b3;
                LDSM_X4(b0, b1r, b2r, b3, wrow + tp * 12544);
                MMA_F16(acc1[2 * tp],     a0, a1, a2, a3, b0,  b1r);
                MMA_F16(acc1[2 * tp + 1], a0, a1, a2, a3, b2r, b3);
            }
        }

        // ----- epilogue: +b1, ReLU, pack C-frags directly into layer2 A-frags -----
        uint32_t hfrag[4][4];
#pragma unroll
        for (int tp = 0; tp < 4; tp++) {
#pragma unroll
            for (int hh = 0; hh < 2; hh++) {
                int t = 2 * tp + hh;
                int n = c * 64 + t * 8 + c2i;
                float bb0 = sB1[n], bb1 = sB1[n + 1];
                float v0 = fmaxf(acc1[t][0] + bb0, 0.f);
                float v1 = fmaxf(acc1[t][1] + bb1, 0.f);
                float v2 = fmaxf(acc1[t][2] + bb0, 0.f);
                float v3 = fmaxf(acc1[t][3] + bb1, 0.f);
                __half2 p0 = __floats2half2_rn(v0, v1);
                __half2 p1 = __floats2half2_rn(v2, v3);
                hfrag[tp][2 * hh]     = *(uint32_t*)&p0;
                hfrag[tp][2 * hh + 1] = *(uint32_t*)&p1;
            }
        }

        // ----- layer 2: out += Hchunk[128x64] @ W2chunk[64x128] -----
        if (c < 7) { CP_WAIT(1); } else { CP_WAIT(0); }   // W2[c] resident
        __syncthreads();

        const uint32_t w2b = sb + OFF_W2 + wLane2;
#pragma unroll
        for (int s2 = 0; s2 < 4; s2++) {
            uint32_t ha0 = hfrag[s2][0], ha1 = hfrag[s2][1];
            uint32_t ha2 = hfrag[s2][2], ha3 = hfrag[s2][3];
#pragma unroll
            for (int t2p = 0; t2p < 8; t2p++) {
                uint32_t b0, b1r, b2r, b3;
                LDSM_X4(b0, b1r, b2r, b3, w2b + s2 * 32 + t2p * 2304);
                MMA_F16(acc2[2 * t2p],     ha0, ha1, ha2, ha3, b0,  b1r);
                MMA_F16(acc2[2 * t2p + 1], ha0, ha1, ha2, ha3, b2r, b3);
            }
        }
        __syncthreads();               // W2 buffer free for next chunk
        if (c < 7) { issue_w2(c + 1); CP_COMMIT(); }
    }

    // ---- output: + b2, two rows per thread per tile ----
    const int g    = lane >> 2;
    const int row0 = warp * 16 + g;
    const int er0  = e0 + row0;
    float* orow0 = out + (size_t)er0 * 128;
#pragma unroll
    for (int t2 = 0; t2 < 16; t2++) {
        int n = t2 * 8 + c2i;
        float bb0 = sB2[n], bb1 = sB2[n + 1];
        if (er0 < N_EDGES) {
            float2 v = make_float2(acc2[t2][0] + bb0, acc2[t2][1] + bb1);
            *(float2*)(orow0 + n) = v;
        }
        if (er0 + 8 < N_EDGES) {
            float2 v = make_float2(acc2[t2][2] + bb0, acc2[t2][3] + bb1);
            *(float2*)(orow0 + (size_t)8 * 128 + n) = v;
        }
    }
}

// ---------------------------------------------------------------------------
extern "C" void kernel_launch(void* const* d_in, const int* in_sizes, int n_in,
                              void* d_out, int out_size) {
    const float* x  = (const float*)d_in[0];
    const int*   ei = (const int*)d_in[1];
    const float* ea = (const float*)d_in[2];
    const float* W1 = (const float*)d_in[3];
    const float* b1 = (const float*)d_in[4];
    const float* W2 = (const float*)d_in[5];
    const float* b2 = (const float*)d_in[6];
    float* out = (float*)d_out;

    cvt_weights_kernel<<<1024, 256>>>(W1, W2);

    cudaFuncSetAttribute(edge_mma_kernel, cudaFuncAttributeMaxDynamicSharedMemorySize, SMEM_TOTAL);
    int grid = (N_EDGES + 127) / 128;  // 3907
    edge_mma_kernel<<<grid, 256, SMEM_TOTAL>>>(x, ei, ea, b1, b2, out);
}

// round 9
// speedup vs baseline: 4.7157x; 1.2318x over previous
#include <cuda_runtime.h>
#include <cuda_fp16.h>
#include <cstdint>

#define N_NODES 50000
#define N_EDGES 500000

// ---------------------------------------------------------------------------
// Transposed f16 weights + precomputed node tables
//   g_W1t[n][k]  n<512, k<384    g_W2t[n][k]  n<128, k<512
//   g_Xs[node][512] = x @ W1[0:128,:]     g_Xt = x @ W1[128:256,:]
// ---------------------------------------------------------------------------
__device__ __half g_W1t[512 * 384];
__device__ __half g_W2t[128 * 512];
__device__ __half g_Xs[(size_t)N_NODES * 512];
__device__ __half g_Xt[(size_t)N_NODES * 512];

__global__ void cvt_weights_kernel(const float* __restrict__ W1,
                                   const float* __restrict__ W2) {
    int idx = blockIdx.x * blockDim.x + threadIdx.x;
    if (idx < 512 * 384) {
        int n = idx / 384, k = idx % 384;
        g_W1t[idx] = __float2half(W1[k * 512 + n]);
    } else if (idx < 512 * 384 + 128 * 512) {
        int j = idx - 512 * 384;
        int n = j / 512, k = j % 512;
        g_W2t[j] = __float2half(W2[k * 128 + n]);
    }
}

// ---------------------------------------------------------------------------
// PTX helpers (baseline features only — plain sm_103 target)
// ---------------------------------------------------------------------------
__device__ __forceinline__ uint32_t s2u(const void* p) {
    uint32_t a;
    asm("{.reg .u64 t; cvta.to.shared.u64 t, %1; cvt.u32.u64 %0, t;}" : "=r"(a) : "l"(p));
    return a;
}
#define CP_ASYNC16(dst, src) \
    asm volatile("cp.async.cg.shared.global [%0], [%1], 16;" :: "r"(dst), "l"(src) : "memory")
#define CP_COMMIT() asm volatile("cp.async.commit_group;" ::: "memory")
#define CP_WAIT(n)  asm volatile("cp.async.wait_group %0;" :: "n"(n) : "memory")

#define LDSM_X4(r0, r1, r2, r3, addr) \
    asm volatile("ldmatrix.sync.aligned.m8n8.x4.shared.b16 {%0,%1,%2,%3}, [%4];" \
                 : "=r"(r0), "=r"(r1), "=r"(r2), "=r"(r3) : "r"(addr))

#define MMA_F16(D, a0, a1, a2, a3, b0, b1) \
    asm volatile("mma.sync.aligned.m16n8k16.row.col.f32.f16.f16.f32 " \
                 "{%0,%1,%2,%3},{%4,%5,%6,%7},{%8,%9},{%0,%1,%2,%3};" \
                 : "+f"((D)[0]), "+f"((D)[1]), "+f"((D)[2]), "+f"((D)[3]) \
                 : "r"(a0), "r"(a1), "r"(a2), "r"(a3), "r"(b0), "r"(b1))

#define STS128(addr, r0, r1, r2, r3) \
    asm volatile("st.shared.v4.b32 [%0], {%1,%2,%3,%4};" \
                 :: "r"(addr), "r"(r0), "r"(r1), "r"(r2), "r"(r3) : "memory")

// A/W1 rows: 128+8 halves = 272 B pitch (272 mod 128 = 16 -> conflict-free ldmatrix)
// W2 rows:   64+8  halves = 144 B pitch
static constexpr uint32_t PITCH_K128 = 272;

// ===========================================================================
// Precompute kernel: table = x[50000x128] @ W1slice[128x512], f16 out.
// blockIdx.y: 0 -> Xs (W1 k rows 0..127), 1 -> Xt (k rows 128..255)
// ===========================================================================
static constexpr uint32_t P_OFF_A = 0;                        // 128 x 272
static constexpr uint32_t P_OFF_W = 34816;                    // 2 x (64 x 272)
static constexpr uint32_t P_WBUF  = 17408;
static constexpr uint32_t P_SMEM  = 69632;

__global__ __launch_bounds__(256, 1) void node_pre_kernel(const float* __restrict__ x) {
    extern __shared__ __align__(1024) char smem[];
    const uint32_t sb = s2u(smem);
    const int tid = threadIdx.x, warp = tid >> 5, lane = tid & 31;
    const int n0 = blockIdx.x * 128;
    const int which = blockIdx.y;
    __half* table = which ? g_Xt : g_Xs;

    auto issue_w = [&](int c, int buf) {
        uint32_t dstb = sb + P_OFF_W + (uint32_t)buf * P_WBUF;
        const __half* src = g_W1t + (size_t)(c * 64) * 384 + which * 128;
#pragma unroll
        for (int i = 0; i < 4; i++) {           // 64 rows x 16 segs = 1024 segs
            int j = tid + i * 256;
            int rr = j >> 4, q = j & 15;
            CP_ASYNC16(dstb + rr * PITCH_K128 + q * 16, src + rr * 384 + q * 8);
        }
    };
    issue_w(0, 0); CP_COMMIT();

    {   // A build: x rows -> f16 smem
        const int r = tid & 127, hb = tid >> 7;
        const int node = min(n0 + r, N_NODES - 1);
        const float* s = x + (size_t)node * 128 + hb * 64;
#pragma unroll
        for (int j = 0; j < 4; j++) {
            const float4* p = (const float4*)(s + j * 16);
            float4 v0 = p[0], v1 = p[1], v2 = p[2], v3 = p[3];
            __half2 h0 = __floats2half2_rn(v0.x, v0.y), h1 = __floats2half2_rn(v0.z, v0.w);
            __half2 h2 = __floats2half2_rn(v1.x, v1.y), h3 = __floats2half2_rn(v1.z, v1.w);
            __half2 h4 = __floats2half2_rn(v2.x, v2.y), h5 = __floats2half2_rn(v2.z, v2.w);
            __half2 h6 = __floats2half2_rn(v3.x, v3.y), h7 = __floats2half2_rn(v3.z, v3.w);
            uint32_t a = sb + P_OFF_A + r * PITCH_K128 + (hb * 64 + j * 16) * 2;
            STS128(a,      *(uint32_t*)&h0, *(uint32_t*)&h1, *(uint32_t*)&h2, *(uint32_t*)&h3);
            STS128(a + 16, *(uint32_t*)&h4, *(uint32_t*)&h5, *(uint32_t*)&h6, *(uint32_t*)&h7);
        }
    }
    __syncthreads();

    const uint32_t aBase = sb + P_OFF_A + (uint32_t)(warp * 16 + (lane & 15)) * PITCH_K128
                         + ((uint32_t)(lane >> 4) << 4);
    const uint32_t wLane = (uint32_t)(lane & 7) * PITCH_K128 + (((uint32_t)(lane >> 3) & 1) << 4)
                         + (uint32_t)(lane >> 4) * (8 * PITCH_K128);
    const int c2i = (lane & 3) * 2;
    const int r0 = warp * 16 + (lane >> 2);
    const int nd0 = n0 + r0, nd1 = nd0 + 8;

    for (int c = 0; c < 8; c++) {
        CP_WAIT(0);
        __syncthreads();
        if (c < 7) { issue_w(c + 1, (c + 1) & 1); CP_COMMIT(); }

        const uint32_t wb = sb + P_OFF_W + (uint32_t)(c & 1) * P_WBUF + wLane;
        float acc[8][4];
#pragma unroll
        for (int t = 0; t < 8; t++)
#pragma unroll
            for (int j = 0; j < 4; j++) acc[t][j] = 0.f;

#pragma unroll
        for (int s = 0; s < 8; s++) {
            uint32_t a0, a1, a2, a3;
            LDSM_X4(a0, a1, a2, a3, aBase + s * 32);
            uint32_t wrow = wb + s * 32;
#pragma unroll
            for (int tp = 0; tp < 4; tp++) {
                uint32_t b0, b1r, b2r, b3;
                LDSM_X4(b0, b1r, b2r, b3, wrow + tp * (16 * PITCH_K128));
                MMA_F16(acc[2 * tp],     a0, a1, a2, a3, b0,  b1r);
                MMA_F16(acc[2 * tp + 1], a0, a1, a2, a3, b2r, b3);
            }
        }
        __syncthreads();

#pragma unroll
        for (int t = 0; t < 8; t++) {
            int n = c * 64 + t * 8 + c2i;
            if (nd0 < N_NODES) {
                __half2 p = __floats2half2_rn(acc[t][0], acc[t][1]);
                *(__half2*)(table + (size_t)nd0 * 512 + n) = p;
            }
            if (nd1 < N_NODES) {
                __half2 p = __floats2half2_rn(acc[t][2], acc[t][3]);
                *(__half2*)(table + (size_t)nd1 * 512 + n) = p;
            }
        }
    }
}

// ===========================================================================
// Edge kernel: layer1 = ea @ W1c (K=128) + gather(Xs,Xt) + b1, ReLU;
//              layer2 = H @ W2 + b2. 128 edges/CTA, 256 threads.
// ===========================================================================
static constexpr uint32_t OFF_A  = 0;        // 128 x 272 = 34816
static constexpr uint32_t OFF_W1 = 34816;    // 2 x (64 x 272) = 34816
static constexpr uint32_t W1_BUF = 17408;
static constexpr uint32_t OFF_W2 = 69632;    // 2 x (128 x 144) = 36864
static constexpr uint32_t W2_BUF = 18432;
static constexpr uint32_t OFF_B1 = 106496;   // 512 f32
static constexpr uint32_t OFF_B2 = 108544;   // 128 f32
static constexpr uint32_t SMEM_TOTAL = 109056;

__global__ __launch_bounds__(256, 1) void edge_mma_kernel(
    const int*   __restrict__ edge_index,
    const float* __restrict__ edge_attr,
    const float* __restrict__ b1,
    const float* __restrict__ b2,
    float* __restrict__ out)
{
    extern __shared__ __align__(1024) char smem[];
    const uint32_t sb = s2u(smem);
    const int tid = threadIdx.x, warp = tid >> 5, lane = tid & 31;
    const int e0 = blockIdx.x * 128;

    float* sB1 = (float*)(smem + OFF_B1);
    float* sB2 = (float*)(smem + OFF_B2);

    auto issue_w1 = [&](int c, int buf) {
        uint32_t dstb = sb + OFF_W1 + (uint32_t)buf * W1_BUF;
        const __half* src = g_W1t + (size_t)(c * 64) * 384 + 256;
#pragma unroll
        for (int i = 0; i < 4; i++) {           // 64 rows x 16 segs = 1024 segs
            int j = tid + i * 256;
            int rr = j >> 4, q = j & 15;
            CP_ASYNC16(dstb + rr * PITCH_K128 + q * 16, src + rr * 384 + q * 8);
        }
    };
    auto issue_w2 = [&](int c, int buf) {
        uint32_t dstb = sb + OFF_W2 + (uint32_t)buf * W2_BUF;
        const __half* src = g_W2t + c * 64;
#pragma unroll
        for (int i = 0; i < 4; i++) {           // 128 rows x 8 segs = 1024 segs
            int j = tid + i * 256;
            int rr = j >> 3, q = j & 7;
            CP_ASYNC16(dstb + rr * 144 + q * 16, src + (size_t)rr * 512 + q * 8);
        }
    };

    issue_w1(0, 0); CP_COMMIT();
    issue_w2(0, 0); CP_COMMIT();

    for (int i = tid; i < 512; i += 256) sB1[i] = b1[i];
    for (int i = tid; i < 128; i += 256) sB2[i] = b2[i];

    {   // A build: edge_attr rows -> f16 smem
        const int r = tid & 127, hb = tid >> 7;
        const int e = min(e0 + r, N_EDGES - 1);
        const float* s = edge_attr + (size_t)e * 128 + hb * 64;
#pragma unroll
        for (int j = 0; j < 4; j++) {
            const float4* p = (const float4*)(s + j * 16);
            float4 v0 = p[0], v1 = p[1], v2 = p[2], v3 = p[3];
            __half2 h0 = __floats2half2_rn(v0.x, v0.y), h1 = __floats2half2_rn(v0.z, v0.w);
            __half2 h2 = __floats2half2_rn(v1.x, v1.y), h3 = __floats2half2_rn(v1.z, v1.w);
            __half2 h4 = __floats2half2_rn(v2.x, v2.y), h5 = __floats2half2_rn(v2.z, v2.w);
            __half2 h6 = __floats2half2_rn(v3.x, v3.y), h7 = __floats2half2_rn(v3.z, v3.w);
            uint32_t a = sb + OFF_A + r * PITCH_K128 + (hb * 64 + j * 16) * 2;
            STS128(a,      *(uint32_t*)&h0, *(uint32_t*)&h1, *(uint32_t*)&h2, *(uint32_t*)&h3);
            STS128(a + 16, *(uint32_t*)&h4, *(uint32_t*)&h5, *(uint32_t*)&h6, *(uint32_t*)&h7);
        }
    }

    // per-lane node pointers for the epilogue gathers
    const int r0 = warp * 16 + (lane >> 2);
    const int ea_ = min(e0 + r0, N_EDGES - 1);
    const int eb_ = min(e0 + r0 + 8, N_EDGES - 1);
    const __half* pxs0 = g_Xs + (size_t)edge_index[ea_] * 512;
    const __half* pxt0 = g_Xt + (size_t)edge_index[N_EDGES + ea_] * 512;
    const __half* pxs1 = g_Xs + (size_t)edge_index[eb_] * 512;
    const __half* pxt1 = g_Xt + (size_t)edge_index[N_EDGES + eb_] * 512;

    __syncthreads();

    const uint32_t aBase = sb + OFF_A + (uint32_t)(warp * 16 + (lane & 15)) * PITCH_K128
                         + ((uint32_t)(lane >> 4) << 4);
    const uint32_t wLane1 = (uint32_t)(lane & 7) * PITCH_K128 + (((uint32_t)(lane >> 3) & 1) << 4)
                          + (uint32_t)(lane >> 4) * (8 * PITCH_K128);
    const uint32_t wLane2 = (uint32_t)(lane & 7) * 144 + (((uint32_t)(lane >> 3) & 1) << 4)
                          + (uint32_t)(lane >> 4) * 1152;
    const int c2i = (lane & 3) * 2;

    float acc2[16][4];
#pragma unroll
    for (int t = 0; t < 16; t++)
#pragma unroll
        for (int j = 0; j < 4; j++) acc2[t][j] = 0.f;

    for (int c = 0; c < 8; c++) {
        CP_WAIT(1);                 // W1[c] resident (W2[c] may still fly)
        __syncthreads();
        if (c < 7) { issue_w1(c + 1, (c + 1) & 1); CP_COMMIT(); }

        // ----- layer 1: A[128x128] @ W1c_chunk[128x64] -----
        const uint32_t wb = sb + OFF_W1 + (uint32_t)(c & 1) * W1_BUF + wLane1;
        float acc1[8][4];
#pragma unroll
        for (int t = 0; t < 8; t++)
#pragma unroll
            for (int j = 0; j < 4; j++) acc1[t][j] = 0.f;

#pragma unroll
        for (int s = 0; s < 8; s++) {
            uint32_t a0, a1, a2, a3;
            LDSM_X4(a0, a1, a2, a3, aBase + s * 32);
            uint32_t wrow = wb + s * 32;
#pragma unroll
            for (int tp = 0; tp < 4; tp++) {
                uint32_t b0, b1r, b2r, b3;
                LDSM_X4(b0, b1r, b2r, b3, wrow + tp * (16 * PITCH_K128));
                MMA_F16(acc1[2 * tp],     a0, a1, a2, a3, b0,  b1r);
                MMA_F16(acc1[2 * tp + 1], a0, a1, a2, a3, b2r, b3);
            }
        }

        // ----- staged gathers: Xs/Xt half2 for this chunk's 64 cols -----
        uint32_t gxs0[8], gxt0[8], gxs1[8], gxt1[8];
#pragma unroll
        for (int t = 0; t < 8; t++) {
            int n = c * 64 + t * 8 + c2i;
            gxs0[t] = *(const uint32_t*)(pxs0 + n);
            gxt0[t] = *(const uint32_t*)(pxt0 + n);
            gxs1[t] = *(const uint32_t*)(pxs1 + n);
            gxt1[t] = *(const uint32_t*)(pxt1 + n);
        }

        // ----- epilogue: + Xs + Xt + b1, ReLU, pack layer2 A-frags -----
        uint32_t hfrag[4][4];
#pragma unroll
        for (int tp = 0; tp < 4; tp++) {
#pragma unroll
            for (int hh = 0; hh < 2; hh++) {
                int t = 2 * tp + hh;
                int n = c * 64 + t * 8 + c2i;
                float bb0 = sB1[n], bb1 = sB1[n + 1];
                float2 s0 = __half22float2(*(__half2*)&gxs0[t]);
                float2 t0 = __half22float2(*(__half2*)&gxt0[t]);
                float2 s1 = __half22float2(*(__half2*)&gxs1[t]);
                float2 t1 = __half22float2(*(__half2*)&gxt1[t]);
                float v0 = fmaxf(acc1[t][0] + s0.x + t0.x + bb0, 0.f);
                float v1 = fmaxf(acc1[t][1] + s0.y + t0.y + bb1, 0.f);
                float v2 = fmaxf(acc1[t][2] + s1.x + t1.x + bb0, 0.f);
                float v3 = fmaxf(acc1[t][3] + s1.y + t1.y + bb1, 0.f);
                __half2 p0 = __floats2half2_rn(v0, v1);
                __half2 p1 = __floats2half2_rn(v2, v3);
                hfrag[tp][2 * hh]     = *(uint32_t*)&p0;
                hfrag[tp][2 * hh + 1] = *(uint32_t*)&p1;
            }
        }

        // ----- layer 2: out += Hchunk[128x64] @ W2chunk[64x128] -----
        if (c < 7) { CP_WAIT(1); } else { CP_WAIT(0); }
        __syncthreads();
        if (c < 7) { issue_w2(c + 1, (c + 1) & 1); CP_COMMIT(); }

        const uint32_t w2b = sb + OFF_W2 + (uint32_t)(c & 1) * W2_BUF + wLane2;
#pragma unroll
        for (int s2 = 0; s2 < 4; s2++) {
            uint32_t ha0 = hfrag[s2][0], ha1 = hfrag[s2][1];
            uint32_t ha2 = hfrag[s2][2], ha3 = hfrag[s2][3];
#pragma unroll
            for (int t2p = 0; t2p < 8; t2p++) {
                uint32_t b0, b1r, b2r, b3;
                LDSM_X4(b0, b1r, b2r, b3, w2b + s2 * 32 + t2p * 2304);
                MMA_F16(acc2[2 * t2p],     ha0, ha1, ha2, ha3, b0,  b1r);
                MMA_F16(acc2[2 * t2p + 1], ha0, ha1, ha2, ha3, b2r, b3);
            }
        }
    }

    // ---- output: + b2 ----
    const int er0 = e0 + r0;
    float* orow0 = out + (size_t)er0 * 128;
#pragma unroll
    for (int t2 = 0; t2 < 16; t2++) {
        int n = t2 * 8 + c2i;
        float bb0 = sB2[n], bb1 = sB2[n + 1];
        if (er0 < N_EDGES) {
            float2 v = make_float2(acc2[t2][0] + bb0, acc2[t2][1] + bb1);
            *(float2*)(orow0 + n) = v;
        }
        if (er0 + 8 < N_EDGES) {
            float2 v = make_float2(acc2[t2][2] + bb0, acc2[t2][3] + bb1);
            *(float2*)(orow0 + (size_t)8 * 128 + n) = v;
        }
    }
}

// ---------------------------------------------------------------------------
extern "C" void kernel_launch(void* const* d_in, const int* in_sizes, int n_in,
                              void* d_out, int out_size) {
    const float* x  = (const float*)d_in[0];
    const int*   ei = (const int*)d_in[1];
    const float* ea = (const float*)d_in[2];
    const float* W1 = (const float*)d_in[3];
    const float* b1 = (const float*)d_in[4];
    const float* W2 = (const float*)d_in[5];
    const float* b2 = (const float*)d_in[6];
    float* out = (float*)d_out;

    cvt_weights_kernel<<<1024, 256>>>(W1, W2);

    cudaFuncSetAttribute(node_pre_kernel, cudaFuncAttributeMaxDynamicSharedMemorySize, P_SMEM);
    dim3 gpre((N_NODES + 127) / 128, 2);
    node_pre_kernel<<<gpre, 256, P_SMEM>>>(x);

    cudaFuncSetAttribute(edge_mma_kernel, cudaFuncAttributeMaxDynamicSharedMemorySize, SMEM_TOTAL);
    int grid = (N_EDGES + 127) / 128;  // 3907
    edge_mma_kernel<<<grid, 256, SMEM_TOTAL>>>(ei, ea, b1, b2, out);
}

// round 11
// speedup vs baseline: 6.3937x; 1.3558x over previous
#include <cuda_runtime.h>
#include <cuda_fp16.h>
#include <cstdint>

#define N_NODES 50000
#define N_EDGES 500000

// ---------------------------------------------------------------------------
// Transposed f16 weights + precomputed node tables
//   g_W1t[n][k]  n<512, k<384    g_W2t[n][k]  n<128, k<512
//   g_Xs[node][512] = x @ W1[0:128,:]     g_Xt = x @ W1[128:256,:]
// ---------------------------------------------------------------------------
__device__ __half g_W1t[512 * 384];
__device__ __half g_W2t[128 * 512];
__device__ __half g_Xs[(size_t)N_NODES * 512];
__device__ __half g_Xt[(size_t)N_NODES * 512];

__global__ void cvt_weights_kernel(const float* __restrict__ W1,
                                   const float* __restrict__ W2) {
    int idx = blockIdx.x * blockDim.x + threadIdx.x;
    if (idx < 512 * 384) {
        int n = idx / 384, k = idx % 384;
        g_W1t[idx] = __float2half(W1[k * 512 + n]);
    } else if (idx < 512 * 384 + 128 * 512) {
        int j = idx - 512 * 384;
        int n = j / 512, k = j % 512;
        g_W2t[j] = __float2half(W2[k * 128 + n]);
    }
}

// ---------------------------------------------------------------------------
// PTX helpers (baseline features only — plain sm_103 target)
// ---------------------------------------------------------------------------
__device__ __forceinline__ uint32_t s2u(const void* p) {
    uint32_t a;
    asm("{.reg .u64 t; cvta.to.shared.u64 t, %1; cvt.u32.u64 %0, t;}" : "=r"(a) : "l"(p));
    return a;
}
#define CP_ASYNC16(dst, src) \
    asm volatile("cp.async.cg.shared.global [%0], [%1], 16;" :: "r"(dst), "l"(src) : "memory")
#define CP_COMMIT() asm volatile("cp.async.commit_group;" ::: "memory")
#define CP_WAIT(n)  asm volatile("cp.async.wait_group %0;" :: "n"(n) : "memory")

#define LDSM_X4(r0, r1, r2, r3, addr) \
    asm volatile("ldmatrix.sync.aligned.m8n8.x4.shared.b16 {%0,%1,%2,%3}, [%4];" \
                 : "=r"(r0), "=r"(r1), "=r"(r2), "=r"(r3) : "r"(addr))

#define MMA_F16(D, a0, a1, a2, a3, b0, b1) \
    asm volatile("mma.sync.aligned.m16n8k16.row.col.f32.f16.f16.f32 " \
                 "{%0,%1,%2,%3},{%4,%5,%6,%7},{%8,%9},{%0,%1,%2,%3};" \
                 : "+f"((D)[0]), "+f"((D)[1]), "+f"((D)[2]), "+f"((D)[3]) \
                 : "r"(a0), "r"(a1), "r"(a2), "r"(a3), "r"(b0), "r"(b1))

#define STS128(addr, r0, r1, r2, r3) \
    asm volatile("st.shared.v4.b32 [%0], {%1,%2,%3,%4};" \
                 :: "r"(addr), "r"(r0), "r"(r1), "r"(r2), "r"(r3) : "memory")

// A/W1 rows: 128+8 halves = 272 B pitch (conflict-free ldmatrix)
// W2 rows:   64+8  halves = 144 B pitch
static constexpr uint32_t PITCH_K128 = 272;

// ===========================================================================
// Precompute kernel: table = x[50000x128] @ W1slice[128x512], f16 out.
// blockIdx.y: 0 -> Xs (W1 k rows 0..127), 1 -> Xt (k rows 128..255)
// ===========================================================================
static constexpr uint32_t P_OFF_A = 0;                        // 128 x 272
static constexpr uint32_t P_OFF_W = 34816;                    // 2 x (64 x 272)
static constexpr uint32_t P_WBUF  = 17408;
static constexpr uint32_t P_SMEM  = 69632;

__global__ __launch_bounds__(256, 1) void node_pre_kernel(const float* __restrict__ x) {
    extern __shared__ __align__(1024) char smem[];
    const uint32_t sb = s2u(smem);
    const int tid = threadIdx.x, warp = tid >> 5, lane = tid & 31;
    const int n0 = blockIdx.x * 128;
    const int which = blockIdx.y;
    __half* table = which ? g_Xt : g_Xs;

    auto issue_w = [&](int c, int buf) {
        uint32_t dstb = sb + P_OFF_W + (uint32_t)buf * P_WBUF;
        const __half* src = g_W1t + (size_t)(c * 64) * 384 + which * 128;
#pragma unroll
        for (int i = 0; i < 4; i++) {           // 64 rows x 16 segs = 1024 segs
            int j = tid + i * 256;
            int rr = j >> 4, q = j & 15;
            CP_ASYNC16(dstb + rr * PITCH_K128 + q * 16, src + rr * 384 + q * 8);
        }
    };
    issue_w(0, 0); CP_COMMIT();

    {   // A build: x rows -> f16 smem
        const int r = tid & 127, hb = tid >> 7;
        const int node = min(n0 + r, N_NODES - 1);
        const float* s = x + (size_t)node * 128 + hb * 64;
#pragma unroll
        for (int j = 0; j < 4; j++) {
            const float4* p = (const float4*)(s + j * 16);
            float4 v0 = p[0], v1 = p[1], v2 = p[2], v3 = p[3];
            __half2 h0 = __floats2half2_rn(v0.x, v0.y), h1 = __floats2half2_rn(v0.z, v0.w);
            __half2 h2 = __floats2half2_rn(v1.x, v1.y), h3 = __floats2half2_rn(v1.z, v1.w);
            __half2 h4 = __floats2half2_rn(v2.x, v2.y), h5 = __floats2half2_rn(v2.z, v2.w);
            __half2 h6 = __floats2half2_rn(v3.x, v3.y), h7 = __floats2half2_rn(v3.z, v3.w);
            uint32_t a = sb + P_OFF_A + r * PITCH_K128 + (hb * 64 + j * 16) * 2;
            STS128(a,      *(uint32_t*)&h0, *(uint32_t*)&h1, *(uint32_t*)&h2, *(uint32_t*)&h3);
            STS128(a + 16, *(uint32_t*)&h4, *(uint32_t*)&h5, *(uint32_t*)&h6, *(uint32_t*)&h7);
        }
    }
    __syncthreads();

    const uint32_t aBase = sb + P_OFF_A + (uint32_t)(warp * 16 + (lane & 15)) * PITCH_K128
                         + ((uint32_t)(lane >> 4) << 4);
    const uint32_t wLane = (uint32_t)(lane & 7) * PITCH_K128 + (((uint32_t)(lane >> 3) & 1) << 4)
                         + (uint32_t)(lane >> 4) * (8 * PITCH_K128);
    const int c2i = (lane & 3) * 2;
    const int r0 = warp * 16 + (lane >> 2);
    const int nd0 = n0 + r0, nd1 = nd0 + 8;

    for (int c = 0; c < 8; c++) {
        CP_WAIT(0);
        __syncthreads();
        if (c < 7) { issue_w(c + 1, (c + 1) & 1); CP_COMMIT(); }

        const uint32_t wb = sb + P_OFF_W + (uint32_t)(c & 1) * P_WBUF + wLane;
        float acc[8][4];
#pragma unroll
        for (int t = 0; t < 8; t++)
#pragma unroll
            for (int j = 0; j < 4; j++) acc[t][j] = 0.f;

#pragma unroll
        for (int s = 0; s < 8; s++) {
            uint32_t a0, a1, a2, a3;
            LDSM_X4(a0, a1, a2, a3, aBase + s * 32);
            uint32_t wrow = wb + s * 32;
#pragma unroll
            for (int tp = 0; tp < 4; tp++) {
                uint32_t b0, b1r, b2r, b3;
                LDSM_X4(b0, b1r, b2r, b3, wrow + tp * (16 * PITCH_K128));
                MMA_F16(acc[2 * tp],     a0, a1, a2, a3, b0,  b1r);
                MMA_F16(acc[2 * tp + 1], a0, a1, a2, a3, b2r, b3);
            }
        }
        __syncthreads();

#pragma unroll
        for (int t = 0; t < 8; t++) {
            int n = c * 64 + t * 8 + c2i;
            if (nd0 < N_NODES) {
                __half2 p = __floats2half2_rn(acc[t][0], acc[t][1]);
                *(__half2*)(table + (size_t)nd0 * 512 + n) = p;
            }
            if (nd1 < N_NODES) {
                __half2 p = __floats2half2_rn(acc[t][2], acc[t][3]);
                *(__half2*)(table + (size_t)nd1 * 512 + n) = p;
            }
        }
    }
}

// ===========================================================================
// Edge kernel: layer1 = ea @ W1c (K=128) + gather(Xs,Xt) + b1, ReLU;
//              layer2 = H @ W2 + b2. 128 edges/CTA, 256 threads.
// Per chunk c: W1 chunk, W2 chunk AND Xs/Xt 128B row slices all prefetched
// via cp.async into double buffers; one wait+sync per chunk.
// ===========================================================================
static constexpr uint32_t OFF_A   = 0;        // 128 x 272 = 34816
static constexpr uint32_t OFF_W1  = 34816;    // 2 x 17408 = 34816
static constexpr uint32_t W1_BUF  = 17408;
static constexpr uint32_t OFF_W2  = 69632;    // 2 x 18432 = 36864
static constexpr uint32_t W2_BUF  = 18432;
static constexpr uint32_t OFF_G   = 106496;   // 2 x 36864 = 73728  ([2][128] x 144B)
static constexpr uint32_t G_BUF   = 36864;
static constexpr uint32_t G_PITCH = 144;
static constexpr uint32_t OFF_B1  = 180224;   // 512 f32
static constexpr uint32_t OFF_B2  = 182272;   // 128 f32
static constexpr uint32_t OFF_IDX = 182784;   // 256 int
static constexpr uint32_t SMEM_TOTAL = 183808;

__global__ __launch_bounds__(256, 1) void edge_mma_kernel(
    const int*   __restrict__ edge_index,
    const float* __restrict__ edge_attr,
    const float* __restrict__ b1,
    const float* __restrict__ b2,
    float* __restrict__ out)
{
    extern __shared__ __align__(1024) char smem[];
    const uint32_t sb = s2u(smem);
    const int tid = threadIdx.x, warp = tid >> 5, lane = tid & 31;
    const int e0 = blockIdx.x * 128;

    float* sB1 = (float*)(smem + OFF_B1);
    float* sB2 = (float*)(smem + OFF_B2);
    int*   sIdx = (int*)(smem + OFF_IDX);   // [0..127]=row(src), [128..255]=col(tgt)

    auto issue_w1 = [&](int c, int buf) {
        uint32_t dstb = sb + OFF_W1 + (uint32_t)buf * W1_BUF;
        const __half* src = g_W1t + (size_t)(c * 64) * 384 + 256;
#pragma unroll
        for (int i = 0; i < 4; i++) {           // 64 rows x 16 segs
            int j = tid + i * 256;
            int rr = j >> 4, q = j & 15;
            CP_ASYNC16(dstb + rr * PITCH_K128 + q * 16, src + rr * 384 + q * 8);
        }
    };
    auto issue_w2 = [&](int c, int buf) {
        uint32_t dstb = sb + OFF_W2 + (uint32_t)buf * W2_BUF;
        const __half* src = g_W2t + c * 64;
#pragma unroll
        for (int i = 0; i < 4; i++) {           // 128 rows x 8 segs
            int j = tid + i * 256;
            int rr = j >> 3, q = j & 7;
            CP_ASYNC16(dstb + rr * 144 + q * 16, src + (size_t)rr * 512 + q * 8);
        }
    };
    // gather chunk c's Xs/Xt 128B row-slices for all 128 edges
    auto issue_g = [&](int c, int buf) {
        uint32_t dstb = sb + OFF_G + (uint32_t)buf * G_BUF;
        const int cc = c * 64;
#pragma unroll
        for (int i = 0; i < 8; i++) {           // 2 tables x 128 edges x 8 segs = 2048
            int j = tid + i * 256;
            int seg = j & 7, edge = (j >> 3) & 127, tbl = j >> 10;
            int row = sIdx[tbl * 128 + edge];
            const __half* src = (tbl ? g_Xt : g_Xs) + (size_t)row * 512 + cc + seg * 8;
            CP_ASYNC16(dstb + (uint32_t)(tbl * 128 + edge) * G_PITCH + seg * 16, src);
        }
    };

    // ---- prologue: indices, biases, A tile (all smem writes), then sync ----
    if (tid < 128) {
        int e = min(e0 + tid, N_EDGES - 1);
        sIdx[tid]       = edge_index[e];
        sIdx[128 + tid] = edge_index[N_EDGES + e];
    }
    for (int i = tid; i < 512; i += 256) sB1[i] = b1[i];
    for (int i = tid; i < 128; i += 256) sB2[i] = b2[i];

    {   // A build: edge_attr rows -> f16 smem
        const int r = tid & 127, hb = tid >> 7;
        const int e = min(e0 + r, N_EDGES - 1);
        const float* s = edge_attr + (size_t)e * 128 + hb * 64;
#pragma unroll
        for (int j = 0; j < 4; j++) {
            const float4* p = (const float4*)(s + j * 16);
            float4 v0 = p[0], v1 = p[1], v2 = p[2], v3 = p[3];
            __half2 h0 = __floats2half2_rn(v0.x, v0.y), h1 = __floats2half2_rn(v0.z, v0.w);
            __half2 h2 = __floats2half2_rn(v1.x, v1.y), h3 = __floats2half2_rn(v1.z, v1.w);
            __half2 h4 = __floats2half2_rn(v2.x, v2.y), h5 = __floats2half2_rn(v2.z, v2.w);
            __half2 h6 = __floats2half2_rn(v3.x, v3.y), h7 = __floats2half2_rn(v3.z, v3.w);
            uint32_t a = sb + OFF_A + r * PITCH_K128 + (hb * 64 + j * 16) * 2;
            STS128(a,      *(uint32_t*)&h0, *(uint32_t*)&h1, *(uint32_t*)&h2, *(uint32_t*)&h3);
            STS128(a + 16, *(uint32_t*)&h4, *(uint32_t*)&h5, *(uint32_t*)&h6, *(uint32_t*)&h7);
        }
    }
    __syncthreads();        // sIdx visible to all before gather issue

    issue_g(0, 0); issue_w1(0, 0); issue_w2(0, 0); CP_COMMIT();

    // ---- per-thread fragment addresses ----
    const uint32_t aBase = sb + OFF_A + (uint32_t)(warp * 16 + (lane & 15)) * PITCH_K128
                         + ((uint32_t)(lane >> 4) << 4);
    const uint32_t wLane1 = (uint32_t)(lane & 7) * PITCH_K128 + (((uint32_t)(lane >> 3) & 1) << 4)
                          + (uint32_t)(lane >> 4) * (8 * PITCH_K128);
    const uint32_t wLane2 = (uint32_t)(lane & 7) * 144 + (((uint32_t)(lane >> 3) & 1) << 4)
                          + (uint32_t)(lane >> 4) * 1152;
    const int c2i = (lane & 3) * 2;
    const int r0 = warp * 16 + (lane >> 2);        // local edge row (0..127)
    // epilogue gather-read base (within G buffer): table0 edge r0
    const uint32_t gRd = (uint32_t)r0 * G_PITCH + (uint32_t)c2i * 2;

    float acc2[16][4];
#pragma unroll
    for (int t = 0; t < 16; t++)
#pragma unroll
        for (int j = 0; j < 4; j++) acc2[t][j] = 0.f;

    for (int c = 0; c < 8; c++) {
        CP_WAIT(0);                 // chunk c data resident
        __syncthreads();            // all warps done with chunk c-1 buffers
        if (c < 7) {
            issue_g(c + 1, (c + 1) & 1);
            issue_w1(c + 1, (c + 1) & 1);
            issue_w2(c + 1, (c + 1) & 1);
            CP_COMMIT();
        }

        // ----- layer 1: A[128x128] @ W1c_chunk[128x64] -----
        const uint32_t wb = sb + OFF_W1 + (uint32_t)(c & 1) * W1_BUF + wLane1;
        float acc1[8][4];
#pragma unroll
        for (int t = 0; t < 8; t++)
#pragma unroll
            for (int j = 0; j < 4; j++) acc1[t][j] = 0.f;

#pragma unroll
        for (int s = 0; s < 8; s++) {
            uint32_t a0, a1, a2, a3;
            LDSM_X4(a0, a1, a2, a3, aBase + s * 32);
            uint32_t wrow = wb + s * 32;
#pragma unroll
            for (int tp = 0; tp < 4; tp++) {
                uint32_t b0, b1r, b2r, b3;
                LDSM_X4(b0, b1r, b2r, b3, wrow + tp * (16 * PITCH_K128));
                MMA_F16(acc1[2 * tp],     a0, a1, a2, a3, b0,  b1r);
                MMA_F16(acc1[2 * tp + 1], a0, a1, a2, a3, b2r, b3);
            }
        }

        // ----- epilogue: + Xs + Xt + b1 (from smem stage), ReLU, pack -----
        const uint32_t gb  = sb + OFF_G + (uint32_t)(c & 1) * G_BUF + gRd;
        uint32_t hfrag[4][4];
#pragma unroll
        for (int tp = 0; tp < 4; tp++) {
#pragma unroll
            for (int hh = 0; hh < 2; hh++) {
                int t = 2 * tp + hh;
                uint32_t off = (uint32_t)t * 16;
                uint32_t us0, ut0, us1, ut1;
                asm volatile("ld.shared.b32 %0, [%1];" : "=r"(us0) : "r"(gb + off));
                asm volatile("ld.shared.b32 %0, [%1];" : "=r"(ut0) : "r"(gb + 128 * G_PITCH + off));
                asm volatile("ld.shared.b32 %0, [%1];" : "=r"(us1) : "r"(gb + 8 * G_PITCH + off));
                asm volatile("ld.shared.b32 %0, [%1];" : "=r"(ut1) : "r"(gb + 136 * G_PITCH + off));
                int n = c * 64 + t * 8 + c2i;
                float bb0 = sB1[n], bb1 = sB1[n + 1];
                float2 s0 = __half22float2(*(__half2*)&us0);
                float2 t0 = __half22float2(*(__half2*)&ut0);
                float2 s1 = __half22float2(*(__half2*)&us1);
                float2 t1 = __half22float2(*(__half2*)&ut1);
                float v0 = fmaxf(acc1[t][0] + s0.x + t0.x + bb0, 0.f);
                float v1 = fmaxf(acc1[t][1] + s0.y + t0.y + bb1, 0.f);
                float v2 = fmaxf(acc1[t][2] + s1.x + t1.x + bb0, 0.f);
                float v3 = fmaxf(acc1[t][3] + s1.y + t1.y + bb1, 0.f);
                __half2 p0 = __floats2half2_rn(v0, v1);
                __half2 p1 = __floats2half2_rn(v2, v3);
                hfrag[tp][2 * hh]     = *(uint32_t*)&p0;
                hfrag[tp][2 * hh + 1] = *(uint32_t*)&p1;
            }
        }

        // ----- layer 2: out += Hchunk[128x64] @ W2chunk[64x128] -----
        const uint32_t w2b = sb + OFF_W2 + (uint32_t)(c & 1) * W2_BUF + wLane2;
#pragma unroll
        for (int s2 = 0; s2 < 4; s2++) {
            uint32_t ha0 = hfrag[s2][0], ha1 = hfrag[s2][1];
            uint32_t ha2 = hfrag[s2][2], ha3 = hfrag[s2][3];
#pragma unroll
            for (int t2p = 0; t2p < 8; t2p++) {
                uint32_t b0, b1r, b2r, b3;
                LDSM_X4(b0, b1r, b2r, b3, w2b + s2 * 32 + t2p * 2304);
                MMA_F16(acc2[2 * t2p],     ha0, ha1, ha2, ha3, b0,  b1r);
                MMA_F16(acc2[2 * t2p + 1], ha0, ha1, ha2, ha3, b2r, b3);
            }
        }
    }

    // ---- output: + b2 ----
    const int er0 = e0 + r0;
    float* orow0 = out + (size_t)er0 * 128;
#pragma unroll
    for (int t2 = 0; t2 < 16; t2++) {
        int n = t2 * 8 + c2i;
        float bb0 = sB2[n], bb1 = sB2[n + 1];
        if (er0 < N_EDGES) {
            float2 v = make_float2(acc2[t2][0] + bb0, acc2[t2][1] + bb1);
            *(float2*)(orow0 + n) = v;
        }
        if (er0 + 8 < N_EDGES) {
            float2 v = make_float2(acc2[t2][2] + bb0, acc2[t2][3] + bb1);
            *(float2*)(orow0 + (size_t)8 * 128 + n) = v;
        }
    }
}

// ---------------------------------------------------------------------------
extern "C" void kernel_launch(void* const* d_in, const int* in_sizes, int n_in,
                              void* d_out, int out_size) {
    const float* x  = (const float*)d_in[0];
    const int*   ei = (const int*)d_in[1];
    const float* ea = (const float*)d_in[2];
    const float* W1 = (const float*)d_in[3];
    const float* b1 = (const float*)d_in[4];
    const float* W2 = (const float*)d_in[5];
    const float* b2 = (const float*)d_in[6];
    float* out = (float*)d_out;

    cvt_weights_kernel<<<1024, 256>>>(W1, W2);

    cudaFuncSetAttribute(node_pre_kernel, cudaFuncAttributeMaxDynamicSharedMemorySize, P_SMEM);
    dim3 gpre((N_NODES + 127) / 128, 2);
    node_pre_kernel<<<gpre, 256, P_SMEM>>>(x);

    cudaFuncSetAttribute(edge_mma_kernel, cudaFuncAttributeMaxDynamicSharedMemorySize, SMEM_TOTAL);
    int grid = (N_EDGES + 127) / 128;  // 3907
    edge_mma_kernel<<<grid, 256, SMEM_TOTAL>>>(ei, ea, b1, b2, out);
}